// round 1
// baseline (speedup 1.0000x reference)
#include <cuda_runtime.h>

// Precomputed matrix power M = linMt^N, row-major [m00 m01 m10 m11].
__device__ float g_M[4];

__global__ void compute_M_kernel(const float* __restrict__ linMt,
                                 const int* __restrict__ Np) {
    // Single thread: compute P = linMt^N in double for accuracy.
    int N = Np[0];
    double a00 = (double)linMt[0], a01 = (double)linMt[1];
    double a10 = (double)linMt[2], a11 = (double)linMt[3];
    double p00 = 1.0, p01 = 0.0, p10 = 0.0, p11 = 1.0;
    for (int i = 0; i < N; i++) {
        double t00 = p00 * a00 + p01 * a10;
        double t01 = p00 * a01 + p01 * a11;
        double t10 = p10 * a00 + p11 * a10;
        double t11 = p10 * a01 + p11 * a11;
        p00 = t00; p01 = t01; p10 = t10; p11 = t11;
    }
    g_M[0] = (float)p00; g_M[1] = (float)p01;
    g_M[2] = (float)p10; g_M[3] = (float)p11;
}

// Streaming apply: out = x @ M, 2 states (one float4) per thread.
__global__ void apply_kernel(const float4* __restrict__ x,
                             float4* __restrict__ out, int n4) {
    int i = blockIdx.x * blockDim.x + threadIdx.x;
    if (i >= n4) return;
    float m00 = g_M[0], m01 = g_M[1], m10 = g_M[2], m11 = g_M[3];
    float4 v = x[i];
    float4 r;
    r.x = v.x * m00 + v.y * m10;
    r.y = v.x * m01 + v.y * m11;
    r.z = v.z * m00 + v.w * m10;
    r.w = v.z * m01 + v.w * m11;
    out[i] = r;
}

// Scalar tail (in case total elements not divisible by 4).
__global__ void apply_tail_kernel(const float* __restrict__ x,
                                  float* __restrict__ out,
                                  int start_pairs, int n_pairs) {
    int i = start_pairs + blockIdx.x * blockDim.x + threadIdx.x;
    if (i >= n_pairs) return;
    float m00 = g_M[0], m01 = g_M[1], m10 = g_M[2], m11 = g_M[3];
    float a = x[2 * i + 0];
    float b = x[2 * i + 1];
    out[2 * i + 0] = a * m00 + b * m10;
    out[2 * i + 1] = a * m01 + b * m11;
}

extern "C" void kernel_launch(void* const* d_in, const int* in_sizes, int n_in,
                              void* d_out, int out_size) {
    const float* x     = (const float*)d_in[0];   // (B, 2) float32
    const float* linMt = (const float*)d_in[1];   // (2, 2) float32
    const int*   Np    = (const int*)d_in[2];     // scalar N
    float* out = (float*)d_out;

    int total = in_sizes[0];       // B * 2 floats
    int n4 = total / 4;            // float4 chunks (2 states each)

    compute_M_kernel<<<1, 1>>>(linMt, Np);

    if (n4 > 0) {
        int threads = 256;
        int blocks = (n4 + threads - 1) / threads;
        apply_kernel<<<blocks, threads>>>((const float4*)x, (float4*)out, n4);
    }

    int rem_floats = total - n4 * 4;       // 0 or 2 (elements come in pairs)
    if (rem_floats > 0) {
        int n_pairs = total / 2;
        int start_pairs = (n4 * 4) / 2;
        int tail = n_pairs - start_pairs;
        apply_tail_kernel<<<1, (tail + 31) / 32 * 32>>>(x, out, start_pairs, n_pairs);
    }
}

// round 2
// speedup vs baseline: 2.7871x; 2.7871x over previous
#include <cuda_runtime.h>

// Precomputed matrix power M = linMt^N, row-major [m00 m01 m10 m11].
__device__ float g_M[4];

// Binary exponentiation in double: ~log2(N) square/multiply steps instead of N.
__global__ void compute_M_kernel(const float* __restrict__ linMt,
                                 const int* __restrict__ Np) {
    int n = Np[0];
    // base = linMt
    double b00 = (double)linMt[0], b01 = (double)linMt[1];
    double b10 = (double)linMt[2], b11 = (double)linMt[3];
    // p = identity
    double p00 = 1.0, p01 = 0.0, p10 = 0.0, p11 = 1.0;
    while (n > 0) {
        if (n & 1) {
            double t00 = p00 * b00 + p01 * b10;
            double t01 = p00 * b01 + p01 * b11;
            double t10 = p10 * b00 + p11 * b10;
            double t11 = p10 * b01 + p11 * b11;
            p00 = t00; p01 = t01; p10 = t10; p11 = t11;
        }
        n >>= 1;
        if (n > 0) {
            double s00 = b00 * b00 + b01 * b10;
            double s01 = b00 * b01 + b01 * b11;
            double s10 = b10 * b00 + b11 * b10;
            double s11 = b10 * b01 + b11 * b11;
            b00 = s00; b01 = s01; b10 = s10; b11 = s11;
        }
    }
    g_M[0] = (float)p00; g_M[1] = (float)p01;
    g_M[2] = (float)p10; g_M[3] = (float)p11;
}

// Streaming apply: out = x @ M. Each thread handles VEC=4 float4s (8 states),
// issued as independent loads for MLP, block-contiguous for coalescing.
#define VEC 4
__global__ void __launch_bounds__(256) apply_kernel(const float4* __restrict__ x,
                                                    float4* __restrict__ out,
                                                    int n4) {
    const float m00 = g_M[0], m01 = g_M[1], m10 = g_M[2], m11 = g_M[3];
    int base = (blockIdx.x * blockDim.x) * VEC + threadIdx.x;

    float4 v[VEC];
    int idx[VEC];
    bool ok[VEC];
#pragma unroll
    for (int j = 0; j < VEC; j++) {
        idx[j] = base + j * 256;
        ok[j] = idx[j] < n4;
        if (ok[j]) v[j] = x[idx[j]];
    }
#pragma unroll
    for (int j = 0; j < VEC; j++) {
        if (ok[j]) {
            float4 r;
            r.x = v[j].x * m00 + v[j].y * m10;
            r.y = v[j].x * m01 + v[j].y * m11;
            r.z = v[j].z * m00 + v[j].w * m10;
            r.w = v[j].z * m01 + v[j].w * m11;
            out[idx[j]] = r;
        }
    }
}

// Scalar tail (in case total elements not divisible by 4).
__global__ void apply_tail_kernel(const float* __restrict__ x,
                                  float* __restrict__ out,
                                  int start_pairs, int n_pairs) {
    int i = start_pairs + blockIdx.x * blockDim.x + threadIdx.x;
    if (i >= n_pairs) return;
    float m00 = g_M[0], m01 = g_M[1], m10 = g_M[2], m11 = g_M[3];
    float a = x[2 * i + 0];
    float b = x[2 * i + 1];
    out[2 * i + 0] = a * m00 + b * m10;
    out[2 * i + 1] = a * m01 + b * m11;
}

extern "C" void kernel_launch(void* const* d_in, const int* in_sizes, int n_in,
                              void* d_out, int out_size) {
    const float* x     = (const float*)d_in[0];   // (B, 2) float32
    const float* linMt = (const float*)d_in[1];   // (2, 2) float32
    const int*   Np    = (const int*)d_in[2];     // scalar N
    float* out = (float*)d_out;

    int total = in_sizes[0];       // B * 2 floats
    int n4 = total / 4;            // float4 chunks (2 states each)

    compute_M_kernel<<<1, 1>>>(linMt, Np);

    if (n4 > 0) {
        int threads = 256;
        int per_block = threads * VEC;
        int blocks = (n4 + per_block - 1) / per_block;
        apply_kernel<<<blocks, threads>>>((const float4*)x, (float4*)out, n4);
    }

    int rem_floats = total - n4 * 4;       // 0 or 2 (elements come in pairs)
    if (rem_floats > 0) {
        int n_pairs = total / 2;
        int start_pairs = (n4 * 4) / 2;
        int tail = n_pairs - start_pairs;
        apply_tail_kernel<<<1, (tail + 31) / 32 * 32>>>(x, out, start_pairs, n_pairs);
    }
}

// round 4
// speedup vs baseline: 3.2734x; 1.1745x over previous
#include <cuda_runtime.h>

// Fused kernel: per-block, thread 0 computes M = linMt^N by fp32 binary
// exponentiation (~130-cycle serial chain) into smem; all threads then
// stream out = x @ M with VEC float4 loads per thread.
#define VEC 4

__global__ void __launch_bounds__(256) fused_kernel(
    const float4* __restrict__ x, float4* __restrict__ out, int n4,
    const float* __restrict__ linMt, const int* __restrict__ Np,
    const float* __restrict__ xs, float* __restrict__ outs, int n_pairs)
{
    __shared__ float sM[4];
    if (threadIdx.x == 0) {
        int n = Np[0];
        float b00 = linMt[0], b01 = linMt[1];
        float b10 = linMt[2], b11 = linMt[3];
        float p00 = 1.f, p01 = 0.f, p10 = 0.f, p11 = 1.f;
        while (n > 0) {
            if (n & 1) {
                float t00 = fmaf(p00, b00, p01 * b10);
                float t01 = fmaf(p00, b01, p01 * b11);
                float t10 = fmaf(p10, b00, p11 * b10);
                float t11 = fmaf(p10, b01, p11 * b11);
                p00 = t00; p01 = t01; p10 = t10; p11 = t11;
            }
            n >>= 1;
            if (n > 0) {
                float s00 = fmaf(b00, b00, b01 * b10);
                float s01 = fmaf(b00, b01, b01 * b11);
                float s10 = fmaf(b10, b00, b11 * b10);
                float s11 = fmaf(b10, b01, b11 * b11);
                b00 = s00; b01 = s01; b10 = s10; b11 = s11;
            }
        }
        sM[0] = p00; sM[1] = p01; sM[2] = p10; sM[3] = p11;
    }
    __syncthreads();
    const float m00 = sM[0], m01 = sM[1], m10 = sM[2], m11 = sM[3];

    int base = (blockIdx.x * blockDim.x) * VEC + threadIdx.x;
#pragma unroll
    for (int j = 0; j < VEC; j++) {
        int idx = base + j * 256;
        if (idx < n4) {
            float4 v = x[idx];
            float4 r;
            r.x = fmaf(v.x, m00, v.y * m10);
            r.y = fmaf(v.x, m01, v.y * m11);
            r.z = fmaf(v.z, m00, v.w * m10);
            r.w = fmaf(v.z, m01, v.w * m11);
            out[idx] = r;
        }
    }

    // Tail: at most one leftover state pair if total floats % 4 != 0.
    if (blockIdx.x == 0 && threadIdx.x == 0) {
        for (int p = n4 * 2; p < n_pairs; p++) {
            float a = xs[2 * p + 0];
            float b = xs[2 * p + 1];
            outs[2 * p + 0] = fmaf(a, m00, b * m10);
            outs[2 * p + 1] = fmaf(a, m01, b * m11);
        }
    }
}

extern "C" void kernel_launch(void* const* d_in, const int* in_sizes, int n_in,
                              void* d_out, int out_size) {
    const float* x     = (const float*)d_in[0];   // (B, 2) float32
    const float* linMt = (const float*)d_in[1];   // (2, 2) float32
    const int*   Np    = (const int*)d_in[2];     // scalar N
    float* out = (float*)d_out;

    int total   = in_sizes[0];   // B * 2 floats
    int n4      = total / 4;     // float4 chunks (2 states each)
    int n_pairs = total / 2;

    int threads = 256;
    int per_block = threads * VEC;
    int blocks = (n4 + per_block - 1) / per_block;
    if (blocks < 1) blocks = 1;

    fused_kernel<<<blocks, threads>>>((const float4*)x, (float4*)out, n4,
                                      linMt, Np, x, out, n_pairs);
}